// round 4
// baseline (speedup 1.0000x reference)
#include <cuda_runtime.h>
#include <stdint.h>

#define NTOK  16384
#define DPROJ 1024
#define BM 128
#define BN 128
#define BK 32
#define ASTRIDE 36
#define MAX_MTILES 132   // sum over clusters of ceil(cnt/128) <= 131

__device__ int g_count[4];
__device__ int g_perm[4 * NTOK];

__global__ void k_classify(const int* __restrict__ inp) {
    int t = blockIdx.x * 256 + threadIdx.x;
    int tok = inp[t];
    int c = (tok >= 200000) ? 3 : (tok >= 40000) ? 2 : (tok >= 20000) ? 1 : 0;
    int pos = atomicAdd(&g_count[c], 1);
    g_perm[c * NTOK + pos] = t;
}

__device__ __forceinline__ float tf32r(float x) {
    uint32_t u;
    asm("cvt.rna.tf32.f32 %0, %1;" : "=r"(u) : "f"(x));
    return __uint_as_float(u);
}
__device__ __forceinline__ float4 tf32r4(float4 v) {
    return make_float4(tf32r(v.x), tf32r(v.y), tf32r(v.z), tf32r(v.w));
}

// Fused adaptive-embedding GEMM, all 4 clusters, block 128x128, warp 32x64.
// C[m,n] = 32 * sum_k emb[row_m,k] * proj[n,k]   (tf32 MMA, fp32 accum)
__global__ void __launch_bounds__(256)
k_fused(const int* __restrict__ inp,
        const float* __restrict__ emb0, const float* __restrict__ proj0,
        const float* __restrict__ emb1, const float* __restrict__ proj1,
        const float* __restrict__ emb2, const float* __restrict__ proj2,
        const float* __restrict__ emb3, const float* __restrict__ proj3,
        float* __restrict__ out)
{
    extern __shared__ float smem[];
    float* As = smem;                                  // [2][BM][ASTRIDE]
    float* Bs = smem + 2 * BM * ASTRIDE;               // [2][BN][ASTRIDE]
    int* s_tok = (int*)(Bs + 2 * BN * ASTRIDE);        // [BM]
    int* s_row = s_tok + BM;                           // [BM]

    // ---- map blockIdx.y -> (cluster, mtile) ----
    int y = blockIdx.y;
    int cluster = -1, mtile = 0, acc = 0;
#pragma unroll
    for (int c = 0; c < 4; c++) {
        int tiles = (g_count[c] + BM - 1) >> 7;
        if (cluster < 0 && y < acc + tiles) { cluster = c; mtile = y - acc; }
        acc += tiles;
    }
    if (cluster < 0) return;

    const float* emb;  const float* proj;  int D, lo;
    switch (cluster) {
        case 0:  emb = emb0; proj = proj0; D = 1024; lo = 0;      break;
        case 1:  emb = emb1; proj = proj1; D = 256;  lo = 20000;  break;
        case 2:  emb = emb2; proj = proj2; D = 64;   lo = 40000;  break;
        default: emb = emb3; proj = proj3; D = 16;   lo = 200000; break;
    }

    const int tid = threadIdx.x;
    const int cnt = g_count[cluster];

    if (tid < BM) {
        int m = mtile * BM + tid;
        int t = -1, row = 0;
        if (m < cnt) { t = g_perm[cluster * NTOK + m]; row = inp[t] - lo; }
        s_tok[tid] = t;
        s_row[tid] = row;
    }
    __syncthreads();

    // ---- loader mapping: thread -> (rows ra+32j, k-quad qa) ----
    const int qa = tid & 7;
    const int ra = tid >> 3;
    const int nb = blockIdx.x * BN;

    const float* aptr[4];
#pragma unroll
    for (int j = 0; j < 4; j++)
        aptr[j] = emb + (size_t)s_row[ra + 32 * j] * D + qa * 4;
    const float* bptr[4];
#pragma unroll
    for (int j = 0; j < 4; j++)
        bptr[j] = proj + (size_t)(nb + ra + 32 * j) * D + qa * 4;

    // ---- warp / fragment mapping: 8 warps = 4m x 2n, warp tile 32x64 ----
    const int wid  = tid >> 5, lane = tid & 31;
    const int gid  = lane >> 2, tg = lane & 3;
    const int wm   = (wid >> 1) * 32;   // 4 warps along M
    const int wn   = (wid & 1) * 64;    // 2 warps along N

    float accum[2][8][4];
#pragma unroll
    for (int i = 0; i < 2; i++)
#pragma unroll
        for (int j = 0; j < 8; j++)
#pragma unroll
            for (int k = 0; k < 4; k++) accum[i][j][k] = 0.f;

    const float4 fz = make_float4(0.f, 0.f, 0.f, 0.f);
    float4 pa[4], pb[4];

    // prologue: fetch k-block 0, fill stage 0
    {
        bool kok = (qa * 4) < D;
#pragma unroll
        for (int j = 0; j < 4; j++) pa[j] = kok ? *(const float4*)(aptr[j]) : fz;
#pragma unroll
        for (int j = 0; j < 4; j++) pb[j] = kok ? *(const float4*)(bptr[j]) : fz;
#pragma unroll
        for (int j = 0; j < 4; j++)
            *(float4*)&As[(ra + 32 * j) * ASTRIDE + qa * 4] = tf32r4(pa[j]);
#pragma unroll
        for (int j = 0; j < 4; j++)
            *(float4*)&Bs[(ra + 32 * j) * ASTRIDE + qa * 4] = tf32r4(pb[j]);
    }
    __syncthreads();

    int buf = 0;
    for (int kb = 0; kb < D; kb += BK) {
        const int nkb = kb + BK;
        const bool have_next = nkb < D;

        // prefetch next k-block into registers (overlaps with MMA below)
        if (have_next) {
            bool kok = (nkb + qa * 4) < D;
#pragma unroll
            for (int j = 0; j < 4; j++) pa[j] = kok ? *(const float4*)(aptr[j] + nkb) : fz;
#pragma unroll
            for (int j = 0; j < 4; j++) pb[j] = kok ? *(const float4*)(bptr[j] + nkb) : fz;
        }

        const float* Ab = As + buf * BM * ASTRIDE;
        const float* Bb = Bs + buf * BN * ASTRIDE;

        // fragment double-buffer over the 4 ks steps
        uint32_t a[2][2][4], b[2][8][2];

#define LOAD_FRAGS(slot, ksi)                                                   \
        do {                                                                    \
            const int kk = (ksi) * 8;                                           \
            _Pragma("unroll")                                                   \
            for (int mi = 0; mi < 2; mi++) {                                    \
                int m = wm + mi * 16 + gid;                                     \
                a[slot][mi][0] = __float_as_uint(Ab[(m    ) * ASTRIDE + kk + tg    ]); \
                a[slot][mi][1] = __float_as_uint(Ab[(m + 8) * ASTRIDE + kk + tg    ]); \
                a[slot][mi][2] = __float_as_uint(Ab[(m    ) * ASTRIDE + kk + tg + 4]); \
                a[slot][mi][3] = __float_as_uint(Ab[(m + 8) * ASTRIDE + kk + tg + 4]); \
            }                                                                   \
            _Pragma("unroll")                                                   \
            for (int ni = 0; ni < 8; ni++) {                                    \
                int n = wn + ni * 8 + gid;                                      \
                b[slot][ni][0] = __float_as_uint(Bb[n * ASTRIDE + kk + tg    ]); \
                b[slot][ni][1] = __float_as_uint(Bb[n * ASTRIDE + kk + tg + 4]); \
            }                                                                   \
        } while (0)

        LOAD_FRAGS(0, 0);
#pragma unroll
        for (int ks = 0; ks < 4; ks++) {
            const int cur = ks & 1;
            if (ks < 3) LOAD_FRAGS(cur ^ 1, ks + 1);
#pragma unroll
            for (int mi = 0; mi < 2; mi++)
#pragma unroll
                for (int ni = 0; ni < 8; ni++) {
                    asm volatile(
                        "mma.sync.aligned.m16n8k8.row.col.f32.tf32.tf32.f32 "
                        "{%0,%1,%2,%3}, {%4,%5,%6,%7}, {%8,%9}, {%0,%1,%2,%3};"
                        : "+f"(accum[mi][ni][0]), "+f"(accum[mi][ni][1]),
                          "+f"(accum[mi][ni][2]), "+f"(accum[mi][ni][3])
                        : "r"(a[cur][mi][0]), "r"(a[cur][mi][1]),
                          "r"(a[cur][mi][2]), "r"(a[cur][mi][3]),
                          "r"(b[cur][ni][0]), "r"(b[cur][ni][1]));
                }
        }
#undef LOAD_FRAGS

        // stage next k-block into the other buffer
        if (have_next) {
            float* An = As + (buf ^ 1) * BM * ASTRIDE;
            float* Bn = Bs + (buf ^ 1) * BN * ASTRIDE;
#pragma unroll
            for (int j = 0; j < 4; j++)
                *(float4*)&An[(ra + 32 * j) * ASTRIDE + qa * 4] = tf32r4(pa[j]);
#pragma unroll
            for (int j = 0; j < 4; j++)
                *(float4*)&Bn[(ra + 32 * j) * ASTRIDE + qa * 4] = tf32r4(pb[j]);
        }
        __syncthreads();
        buf ^= 1;
    }

    // ---- epilogue: scale by 32, scatter to out[token, :] ----
#pragma unroll
    for (int mi = 0; mi < 2; mi++) {
#pragma unroll
        for (int half = 0; half < 2; half++) {
            int rl = wm + mi * 16 + gid + half * 8;
            int t  = s_tok[rl];
            if (t >= 0) {
                float* op = out + (size_t)t * DPROJ + nb + wn;
#pragma unroll
                for (int ni = 0; ni < 8; ni++) {
                    float2 v;
                    v.x = accum[mi][ni][half * 2 + 0] * 32.f;
                    v.y = accum[mi][ni][half * 2 + 1] * 32.f;
                    *(float2*)(op + ni * 8 + tg * 2) = v;
                }
            }
        }
    }
}

extern "C" void kernel_launch(void* const* d_in, const int* in_sizes, int n_in,
                              void* d_out, int out_size) {
    const int*   inp   = (const int*)d_in[0];
    const float* emb0  = (const float*)d_in[1];
    const float* proj0 = (const float*)d_in[2];
    const float* emb1  = (const float*)d_in[3];
    const float* proj1 = (const float*)d_in[4];
    const float* emb2  = (const float*)d_in[5];
    const float* proj2 = (const float*)d_in[6];
    const float* emb3  = (const float*)d_in[7];
    const float* proj3 = (const float*)d_in[8];
    float* out = (float*)d_out;

    const int smem_bytes = (2 * BM * ASTRIDE + 2 * BN * ASTRIDE) * 4 + 2 * BM * 4;
    cudaFuncSetAttribute(k_fused, cudaFuncAttributeMaxDynamicSharedMemorySize,
                         smem_bytes);

    void* gcnt = nullptr;
    cudaGetSymbolAddress(&gcnt, g_count);
    cudaMemsetAsync(gcnt, 0, 4 * sizeof(int));

    k_classify<<<NTOK / 256, 256>>>(inp);

    dim3 grid(DPROJ / BN, MAX_MTILES);   // (8, 132)
    k_fused<<<grid, 256, smem_bytes>>>(inp, emb0, proj0, emb1, proj1,
                                       emb2, proj2, emb3, proj3, out);
}

// round 6
// speedup vs baseline: 1.0949x; 1.0949x over previous
#include <cuda_runtime.h>
#include <cuda_fp16.h>
#include <stdint.h>

#define NTOK  16384
#define DPROJ 1024
#define BM 128
#define BN 128
#define BK 32            // k per smem stage (halves)
#define HSTRIDE 40       // half-element row stride (20 words; conflict-free frags)
#define MAX_MTILES 132

__device__ int g_count[4];
__device__ int g_perm[4 * NTOK];

__global__ void k_classify(const int* __restrict__ inp) {
    int t = blockIdx.x * 256 + threadIdx.x;
    int tok = inp[t];
    int c = (tok >= 200000) ? 3 : (tok >= 40000) ? 2 : (tok >= 20000) ? 1 : 0;
    int pos = atomicAdd(&g_count[c], 1);
    g_perm[c * NTOK + pos] = t;
}

__device__ __forceinline__ uint4 pack8(float4 v0, float4 v1) {
    __half2 h0 = __float22half2_rn(make_float2(v0.x, v0.y));
    __half2 h1 = __float22half2_rn(make_float2(v0.z, v0.w));
    __half2 h2 = __float22half2_rn(make_float2(v1.x, v1.y));
    __half2 h3 = __float22half2_rn(make_float2(v1.z, v1.w));
    uint4 r;
    r.x = *(uint32_t*)&h0; r.y = *(uint32_t*)&h1;
    r.z = *(uint32_t*)&h2; r.w = *(uint32_t*)&h3;
    return r;
}

// Fused adaptive-embedding GEMM, all 4 clusters. fp16 MMA (m16n8k16), fp32 accum.
// C[m,n] = 32 * sum_k emb[row_m,k] * proj[n,k]
__global__ void __launch_bounds__(256)
k_fused(const int* __restrict__ inp,
        const float* __restrict__ emb0, const float* __restrict__ proj0,
        const float* __restrict__ emb1, const float* __restrict__ proj1,
        const float* __restrict__ emb2, const float* __restrict__ proj2,
        const float* __restrict__ emb3, const float* __restrict__ proj3,
        float* __restrict__ out)
{
    extern __shared__ __half smh[];
    __half* As = smh;                                  // [2][BM][HSTRIDE]
    __half* Bs = smh + 2 * BM * HSTRIDE;               // [2][BN][HSTRIDE]
    int* s_tok = (int*)(Bs + 2 * BN * HSTRIDE);        // [BM]
    int* s_row = s_tok + BM;                           // [BM]

    // ---- map blockIdx.y -> (cluster, mtile) ----
    int y = blockIdx.y;
    int cluster = -1, mtile = 0, acc = 0;
#pragma unroll
    for (int c = 0; c < 4; c++) {
        int tiles = (g_count[c] + BM - 1) >> 7;
        if (cluster < 0 && y < acc + tiles) { cluster = c; mtile = y - acc; }
        acc += tiles;
    }
    if (cluster < 0) return;

    const float* emb;  const float* proj;  int D, lo;
    switch (cluster) {
        case 0:  emb = emb0; proj = proj0; D = 1024; lo = 0;      break;
        case 1:  emb = emb1; proj = proj1; D = 256;  lo = 20000;  break;
        case 2:  emb = emb2; proj = proj2; D = 64;   lo = 40000;  break;
        default: emb = emb3; proj = proj3; D = 16;   lo = 200000; break;
    }

    const int tid = threadIdx.x;
    const int cnt = g_count[cluster];

    if (tid < BM) {
        int m = mtile * BM + tid;
        int t = -1, row = 0;
        if (m < cnt) { t = g_perm[cluster * NTOK + m]; row = inp[t] - lo; }
        s_tok[tid] = t;
        s_row[tid] = row;
    }
    __syncthreads();

    // ---- loader mapping: thread -> (row, 16-half k-group); 2 threads/row ----
    const int lrow = tid >> 1;            // 0..127
    const int lh   = (tid & 1) * 16;      // k offset within stage (0 or 16)
    const int nb   = blockIdx.x * BN;

    const float* ag = emb  + (size_t)s_row[lrow] * D + lh;
    const float* bg = proj + (size_t)(nb + lrow) * D + lh;
    const int sidx = lrow * HSTRIDE + lh; // half index for STS

    // ---- warp / fragment mapping: 8 warps = 4m x 2n, warp tile 32x64 ----
    const int wid  = tid >> 5, lane = tid & 31;
    const int gid  = lane >> 2, tg = lane & 3;
    const int wm   = (wid >> 1) * 32;
    const int wn   = (wid & 1) * 64;

    float accum[2][8][4];
#pragma unroll
    for (int i = 0; i < 2; i++)
#pragma unroll
        for (int j = 0; j < 8; j++)
#pragma unroll
            for (int k = 0; k < 4; k++) accum[i][j][k] = 0.f;

    const float4 fz = make_float4(0.f, 0.f, 0.f, 0.f);
    float4 va[4], vb[4];   // 16 floats each = full 16-half group

    // prologue: k-block 0 into stage 0
    {
        bool g = lh < D;   // lh, D multiples of 16 -> whole group valid or not
#pragma unroll
        for (int j = 0; j < 4; j++) {
            va[j] = g ? *(const float4*)(ag + 4 * j) : fz;
            vb[j] = g ? *(const float4*)(bg + 4 * j) : fz;
        }
        *(uint4*)&As[sidx]     = pack8(va[0], va[1]);
        *(uint4*)&As[sidx + 8] = pack8(va[2], va[3]);
        *(uint4*)&Bs[sidx]     = pack8(vb[0], vb[1]);
        *(uint4*)&Bs[sidx + 8] = pack8(vb[2], vb[3]);
    }
    __syncthreads();

    int buf = 0;
    for (int kb = 0; kb < D; kb += BK) {
        const int nkb = kb + BK;
        const bool have_next = nkb < D;

        // prefetch next k-block (overlaps with MMAs)
        if (have_next) {
            bool g = (nkb + lh) < D;
#pragma unroll
            for (int j = 0; j < 4; j++) {
                va[j] = g ? *(const float4*)(ag + nkb + 4 * j) : fz;
                vb[j] = g ? *(const float4*)(bg + nkb + 4 * j) : fz;
            }
        }

        const __half* Ab = As + buf * BM * HSTRIDE;
        const __half* Bb = Bs + buf * BN * HSTRIDE;

#pragma unroll
        for (int ks = 0; ks < 2; ks++) {
            const int kk = ks * 16;
            uint32_t a[2][4], b[8][2];
#pragma unroll
            for (int mi = 0; mi < 2; mi++) {
                int m = wm + mi * 16 + gid;
                a[mi][0] = *(const uint32_t*)&Ab[(m    ) * HSTRIDE + kk + tg * 2    ];
                a[mi][1] = *(const uint32_t*)&Ab[(m + 8) * HSTRIDE + kk + tg * 2    ];
                a[mi][2] = *(const uint32_t*)&Ab[(m    ) * HSTRIDE + kk + tg * 2 + 8];
                a[mi][3] = *(const uint32_t*)&Ab[(m + 8) * HSTRIDE + kk + tg * 2 + 8];
            }
#pragma unroll
            for (int ni = 0; ni < 8; ni++) {
                int n = wn + ni * 8 + gid;
                b[ni][0] = *(const uint32_t*)&Bb[n * HSTRIDE + kk + tg * 2    ];
                b[ni][1] = *(const uint32_t*)&Bb[n * HSTRIDE + kk + tg * 2 + 8];
            }
#pragma unroll
            for (int mi = 0; mi < 2; mi++)
#pragma unroll
                for (int ni = 0; ni < 8; ni++) {
                    asm volatile(
                        "mma.sync.aligned.m16n8k16.row.col.f32.f16.f16.f32 "
                        "{%0,%1,%2,%3}, {%4,%5,%6,%7}, {%8,%9}, {%0,%1,%2,%3};"
                        : "+f"(accum[mi][ni][0]), "+f"(accum[mi][ni][1]),
                          "+f"(accum[mi][ni][2]), "+f"(accum[mi][ni][3])
                        : "r"(a[mi][0]), "r"(a[mi][1]), "r"(a[mi][2]), "r"(a[mi][3]),
                          "r"(b[ni][0]), "r"(b[ni][1]));
                }
        }

        if (have_next) {
            __half* An = As + (buf ^ 1) * BM * HSTRIDE;
            __half* Bn = Bs + (buf ^ 1) * BN * HSTRIDE;
            *(uint4*)&An[sidx]     = pack8(va[0], va[1]);
            *(uint4*)&An[sidx + 8] = pack8(va[2], va[3]);
            *(uint4*)&Bn[sidx]     = pack8(vb[0], vb[1]);
            *(uint4*)&Bn[sidx + 8] = pack8(vb[2], vb[3]);
        }
        __syncthreads();
        buf ^= 1;
    }

    // ---- epilogue: scale by 32, scatter to out[token, :] ----
#pragma unroll
    for (int mi = 0; mi < 2; mi++) {
#pragma unroll
        for (int half = 0; half < 2; half++) {
            int rl = wm + mi * 16 + gid + half * 8;
            int t  = s_tok[rl];
            if (t >= 0) {
                float* op = out + (size_t)t * DPROJ + nb + wn;
#pragma unroll
                for (int ni = 0; ni < 8; ni++) {
                    float2 v;
                    v.x = accum[mi][ni][half * 2 + 0] * 32.f;
                    v.y = accum[mi][ni][half * 2 + 1] * 32.f;
                    *(float2*)(op + ni * 8 + tg * 2) = v;
                }
            }
        }
    }
}

extern "C" void kernel_launch(void* const* d_in, const int* in_sizes, int n_in,
                              void* d_out, int out_size) {
    const int*   inp   = (const int*)d_in[0];
    const float* emb0  = (const float*)d_in[1];
    const float* proj0 = (const float*)d_in[2];
    const float* emb1  = (const float*)d_in[3];
    const float* proj1 = (const float*)d_in[4];
    const float* emb2  = (const float*)d_in[5];
    const float* proj2 = (const float*)d_in[6];
    const float* emb3  = (const float*)d_in[7];
    const float* proj3 = (const float*)d_in[8];
    float* out = (float*)d_out;

    const int smem_bytes = (2 * BM * HSTRIDE + 2 * BN * HSTRIDE) * 2 + 2 * BM * 4;
    cudaFuncSetAttribute(k_fused, cudaFuncAttributeMaxDynamicSharedMemorySize,
                         smem_bytes);

    void* gcnt = nullptr;
    cudaGetSymbolAddress(&gcnt, g_count);
    cudaMemsetAsync(gcnt, 0, 4 * sizeof(int));

    k_classify<<<NTOK / 256, 256>>>(inp);

    dim3 grid(DPROJ / BN, MAX_MTILES);   // (8, 132)
    k_fused<<<grid, 256, smem_bytes>>>(inp, emb0, proj0, emb1, proj1,
                                       emb2, proj2, emb3, proj3, out);
}

// round 7
// speedup vs baseline: 1.4232x; 1.2999x over previous
#include <cuda_runtime.h>
#include <cuda_fp16.h>
#include <stdint.h>

#define NTOK  16384
#define DPROJ 1024
#define BM 128
#define BN 128
#define BK 32            // k halves per stage
#define HSTRIDE 40       // half-element row stride (20 words; conflict-free frags)
#define STAGES 3
#define MAX_MTILES 132

// A compact fp16 regions (16384 rows worst case per cluster)
#define A0 0UL
#define A1 (A0 + 16384UL * 1024)
#define A2 (A1 + 16384UL * 256)
#define A3 (A2 + 16384UL * 64)
#define ATOT (A3 + 16384UL * 16)
// B fp16 regions
#define B0 0UL
#define B1 (B0 + 1024UL * 1024)
#define B2 (B1 + 1024UL * 256)
#define B3 (B2 + 1024UL * 64)
#define BTOT (B3 + 1024UL * 16)

__device__ int g_count[4];
__device__ int g_perm[4 * NTOK];
__device__ __half g_acomp[ATOT];   // gathered emb rows, fp16, g_perm order
__device__ __half g_bh[BTOT];      // proj matrices, fp16

__device__ __forceinline__ uint4 pack8(float4 v0, float4 v1) {
    __half2 h0 = __float22half2_rn(make_float2(v0.x, v0.y));
    __half2 h1 = __float22half2_rn(make_float2(v0.z, v0.w));
    __half2 h2 = __float22half2_rn(make_float2(v1.x, v1.y));
    __half2 h3 = __float22half2_rn(make_float2(v1.z, v1.w));
    uint4 r;
    r.x = *(uint32_t*)&h0; r.y = *(uint32_t*)&h1;
    r.z = *(uint32_t*)&h2; r.w = *(uint32_t*)&h3;
    return r;
}

// y==0: classify tokens.  y==1: convert proj -> fp16 (grid-stride, 8 elems/thread).
__global__ void k_classify_conv(const int* __restrict__ inp,
                                const float* __restrict__ p0, const float* __restrict__ p1,
                                const float* __restrict__ p2, const float* __restrict__ p3)
{
    if (blockIdx.y == 0) {
        if (blockIdx.x < NTOK / 256) {
            int t = blockIdx.x * 256 + threadIdx.x;
            int tok = inp[t];
            int c = (tok >= 200000) ? 3 : (tok >= 40000) ? 2 : (tok >= 20000) ? 1 : 0;
            int pos = atomicAdd(&g_count[c], 1);
            g_perm[c * NTOK + pos] = t;
        }
    } else {
        const int stride = gridDim.x * blockDim.x;
        for (size_t u = blockIdx.x * blockDim.x + threadIdx.x; u < BTOT / 8; u += stride) {
            size_t e = u * 8;
            const float* p; size_t off;
            if (e < B1)      { p = p0; off = e - B0; }
            else if (e < B2) { p = p1; off = e - B1; }
            else if (e < B3) { p = p2; off = e - B2; }
            else             { p = p3; off = e - B3; }
            float4 v0 = *(const float4*)(p + off);
            float4 v1 = *(const float4*)(p + off + 4);
            *(uint4*)&g_bh[e] = pack8(v0, v1);
        }
    }
}

// gather + convert emb rows into g_acomp (16-half units). blockIdx.y = cluster.
__global__ void k_gather(const int* __restrict__ inp,
                         const float* __restrict__ e0, const float* __restrict__ e1,
                         const float* __restrict__ e2, const float* __restrict__ e3)
{
    const int c = blockIdx.y;
    const float* src; int D, lo; size_t base;
    switch (c) {
        case 0:  src = e0; D = 1024; lo = 0;      base = A0; break;
        case 1:  src = e1; D = 256;  lo = 20000;  base = A1; break;
        case 2:  src = e2; D = 64;   lo = 40000;  base = A2; break;
        default: src = e3; D = 16;   lo = 200000; base = A3; break;
    }
    const int cnt = g_count[c];
    const int units = cnt * (D >> 4);
    const int stride = gridDim.x * blockDim.x;
    for (int u = blockIdx.x * blockDim.x + threadIdx.x; u < units; u += stride) {
        int m, koff;
        switch (c) {
            case 0:  m = u >> 6; koff = (u & 63) << 4; break;
            case 1:  m = u >> 4; koff = (u & 15) << 4; break;
            case 2:  m = u >> 2; koff = (u & 3)  << 4; break;
            default: m = u;      koff = 0;             break;
        }
        int row = inp[g_perm[c * NTOK + m]] - lo;
        const float* s = src + (size_t)row * D + koff;
        __half* d = g_acomp + base + (size_t)m * D + koff;
        float4 v0 = *(const float4*)(s);
        float4 v1 = *(const float4*)(s + 4);
        float4 v2 = *(const float4*)(s + 8);
        float4 v3 = *(const float4*)(s + 12);
        *(uint4*)d       = pack8(v0, v1);
        *(uint4*)(d + 8) = pack8(v2, v3);
    }
}

__device__ __forceinline__ void cp16(uint32_t dst, const void* src, int valid) {
    asm volatile("cp.async.cg.shared.global [%0], [%1], 16, %2;"
                 :: "r"(dst), "l"(src), "r"(valid));
}

// Fused GEMM: C[m,n] = 32 * sum_k A[m,k] * B[n,k], fp16 in smem via cp.async.
__global__ void __launch_bounds__(256, 2)
k_fused(float* __restrict__ out)
{
    extern __shared__ __half smh[];
    __half* As = smh;                                   // [STAGES][BM][HSTRIDE]
    __half* Bs = smh + STAGES * BM * HSTRIDE;           // [STAGES][BN][HSTRIDE]
    int* s_tok = (int*)(Bs + STAGES * BN * HSTRIDE);    // [BM]

    // ---- map blockIdx.y -> (cluster, mtile) ----
    int y = blockIdx.y;
    int cluster = -1, mtile = 0, acc = 0;
#pragma unroll
    for (int c = 0; c < 4; c++) {
        int tiles = (g_count[c] + BM - 1) >> 7;
        if (cluster < 0 && y < acc + tiles) { cluster = c; mtile = y - acc; }
        acc += tiles;
    }
    if (cluster < 0) return;

    int D; size_t baseA, baseB;
    switch (cluster) {
        case 0:  D = 1024; baseA = A0; baseB = B0; break;
        case 1:  D = 256;  baseA = A1; baseB = B1; break;
        case 2:  D = 64;   baseA = A2; baseB = B2; break;
        default: D = 16;   baseA = A3; baseB = B3; break;
    }

    const int tid = threadIdx.x;
    const int cnt = g_count[cluster];

    if (tid < BM) {
        int m = mtile * BM + tid;
        s_tok[tid] = (m < cnt) ? g_perm[cluster * NTOK + m] : -1;
    }

    // ---- loader mapping: 2 threads/row, 16 halves each ----
    const int lrow = tid >> 1;
    const int lh   = (tid & 1) * 16;
    const int nb   = blockIdx.x * BN;

    const __half* asrc = g_acomp + baseA + (size_t)(mtile * BM + lrow) * D + lh;
    const __half* bsrc = g_bh    + baseB + (size_t)(nb + lrow) * D + lh;

    const uint32_t a_smem = (uint32_t)__cvta_generic_to_shared(As) + (lrow * HSTRIDE + lh) * 2;
    const uint32_t b_smem = (uint32_t)__cvta_generic_to_shared(Bs) + (lrow * HSTRIDE + lh) * 2;

    const int nk = (D + BK - 1) / BK;

#define ISSUE(kbi)                                                            \
    do {                                                                      \
        int _buf = (kbi) % STAGES;                                            \
        int _kb  = (kbi) * BK;                                                \
        int _v   = (_kb + lh < D) ? 16 : 0;                                   \
        const __half* _as = _v ? asrc + _kb : asrc;                           \
        const __half* _bs = _v ? bsrc + _kb : bsrc;                           \
        uint32_t _ad = a_smem + _buf * (BM * HSTRIDE * 2);                    \
        uint32_t _bd = b_smem + _buf * (BN * HSTRIDE * 2);                    \
        cp16(_ad,      _as,     _v);                                         \
        cp16(_ad + 16, _as + 8, _v);                                         \
        cp16(_bd,      _bs,     _v);                                         \
        cp16(_bd + 16, _bs + 8, _v);                                         \
    } while (0)

    // prologue: issue stages 0..STAGES-2
#pragma unroll
    for (int s = 0; s < STAGES - 1; s++) {
        if (s < nk) ISSUE(s);
        asm volatile("cp.async.commit_group;");
    }

    // ---- warp / fragment mapping: 8 warps = 4m x 2n, warp tile 32x64 ----
    const int wid  = tid >> 5, lane = tid & 31;
    const int gid  = lane >> 2, tg = lane & 3;
    const int wm   = (wid >> 1) * 32;
    const int wn   = (wid & 1) * 64;

    float accum[2][8][4];
#pragma unroll
    for (int i = 0; i < 2; i++)
#pragma unroll
        for (int j = 0; j < 8; j++)
#pragma unroll
            for (int k = 0; k < 4; k++) accum[i][j][k] = 0.f;

    for (int kbi = 0; kbi < nk; kbi++) {
        asm volatile("cp.async.wait_group 1;");
        __syncthreads();   // stage kbi data visible to all; also fences prior MMA reads

        const __half* Ab = As + (kbi % STAGES) * BM * HSTRIDE;
        const __half* Bb = Bs + (kbi % STAGES) * BN * HSTRIDE;

#pragma unroll
        for (int ks = 0; ks < 2; ks++) {
            const int kk = ks * 16;
            uint32_t a[2][4], b[8][2];
#pragma unroll
            for (int mi = 0; mi < 2; mi++) {
                int m = wm + mi * 16 + gid;
                a[mi][0] = *(const uint32_t*)&Ab[(m    ) * HSTRIDE + kk + tg * 2    ];
                a[mi][1] = *(const uint32_t*)&Ab[(m + 8) * HSTRIDE + kk + tg * 2    ];
                a[mi][2] = *(const uint32_t*)&Ab[(m    ) * HSTRIDE + kk + tg * 2 + 8];
                a[mi][3] = *(const uint32_t*)&Ab[(m + 8) * HSTRIDE + kk + tg * 2 + 8];
            }
#pragma unroll
            for (int ni = 0; ni < 8; ni++) {
                int n = wn + ni * 8 + gid;
                b[ni][0] = *(const uint32_t*)&Bb[n * HSTRIDE + kk + tg * 2    ];
                b[ni][1] = *(const uint32_t*)&Bb[n * HSTRIDE + kk + tg * 2 + 8];
            }
#pragma unroll
            for (int mi = 0; mi < 2; mi++)
#pragma unroll
                for (int ni = 0; ni < 8; ni++) {
                    asm volatile(
                        "mma.sync.aligned.m16n8k16.row.col.f32.f16.f16.f32 "
                        "{%0,%1,%2,%3}, {%4,%5,%6,%7}, {%8,%9}, {%0,%1,%2,%3};"
                        : "+f"(accum[mi][ni][0]), "+f"(accum[mi][ni][1]),
                          "+f"(accum[mi][ni][2]), "+f"(accum[mi][ni][3])
                        : "r"(a[mi][0]), "r"(a[mi][1]), "r"(a[mi][2]), "r"(a[mi][3]),
                          "r"(b[ni][0]), "r"(b[ni][1]));
                }
        }

        // issue stage kbi+STAGES-1 (overwrites buf (kbi-1)%S; its readers finished
        // before this iteration's __syncthreads)
        int pf = kbi + STAGES - 1;
        if (pf < nk) ISSUE(pf);
        asm volatile("cp.async.commit_group;");
    }
#undef ISSUE

    // ---- epilogue: scale by 32, scatter to out[token, :] ----
#pragma unroll
    for (int mi = 0; mi < 2; mi++) {
#pragma unroll
        for (int half = 0; half < 2; half++) {
            int rl = wm + mi * 16 + gid + half * 8;
            int t  = s_tok[rl];
            if (t >= 0) {
                float* op = out + (size_t)t * DPROJ + nb + wn;
#pragma unroll
                for (int ni = 0; ni < 8; ni++) {
                    float2 v;
                    v.x = accum[mi][ni][half * 2 + 0] * 32.f;
                    v.y = accum[mi][ni][half * 2 + 1] * 32.f;
                    *(float2*)(op + ni * 8 + tg * 2) = v;
                }
            }
        }
    }
}

extern "C" void kernel_launch(void* const* d_in, const int* in_sizes, int n_in,
                              void* d_out, int out_size) {
    const int*   inp   = (const int*)d_in[0];
    const float* emb0  = (const float*)d_in[1];
    const float* proj0 = (const float*)d_in[2];
    const float* emb1  = (const float*)d_in[3];
    const float* proj1 = (const float*)d_in[4];
    const float* emb2  = (const float*)d_in[5];
    const float* proj2 = (const float*)d_in[6];
    const float* emb3  = (const float*)d_in[7];
    const float* proj3 = (const float*)d_in[8];
    float* out = (float*)d_out;

    const int smem_bytes = STAGES * (BM + BN) * HSTRIDE * 2 + BM * 4;
    cudaFuncSetAttribute(k_fused, cudaFuncAttributeMaxDynamicSharedMemorySize,
                         smem_bytes);

    void* gcnt = nullptr;
    cudaGetSymbolAddress(&gcnt, g_count);
    cudaMemsetAsync(gcnt, 0, 4 * sizeof(int));

    k_classify_conv<<<dim3(680, 2), 256>>>(inp, proj0, proj1, proj2, proj3);
    k_gather<<<dim3(128, 4), 256>>>(inp, emb0, emb1, emb2, emb3);

    dim3 grid(DPROJ / BN, MAX_MTILES);   // (8, 132)
    k_fused<<<grid, 256, smem_bytes>>>(out);
}

// round 8
// speedup vs baseline: 1.5504x; 1.0893x over previous
#include <cuda_runtime.h>
#include <cuda_fp16.h>
#include <stdint.h>

#define NTOK  16384
#define DPROJ 1024
#define BM 128
#define BN 128
#define BK 32            // k halves per stage
#define HSTRIDE 40       // half row stride (20 words; conflict-free frags/ldmatrix)
#define STAGES 3
#define MAX_MTILES 132

// A fp16 regions, indexed by flat token position t (row t has D_c halves)
#define A0 0UL
#define A1 (A0 + 16384UL * 1024)
#define A2 (A1 + 16384UL * 256)
#define A3 (A2 + 16384UL * 64)
#define ATOT (A3 + 16384UL * 16)
// B fp16 regions
#define B0 0UL
#define B1 (B0 + 1024UL * 1024)
#define B2 (B1 + 1024UL * 256)
#define B3 (B2 + 1024UL * 64)
#define BTOT (B3 + 1024UL * 16)

#define NB16 (BTOT / 16)          // proj conv units (16 halves each)
#define NA16 (NTOK * 64UL)        // emb conv unit space (t * 64 + k16)

__device__ int g_count[4];
__device__ int g_perm[4 * NTOK];
__device__ __half g_ah[ATOT];     // converted emb rows, fp16, t-indexed
__device__ __half g_bh[BTOT];     // proj matrices, fp16

__device__ __forceinline__ uint4 pack8(float4 v0, float4 v1) {
    __half2 h0 = __float22half2_rn(make_float2(v0.x, v0.y));
    __half2 h1 = __float22half2_rn(make_float2(v0.z, v0.w));
    __half2 h2 = __float22half2_rn(make_float2(v1.x, v1.y));
    __half2 h3 = __float22half2_rn(make_float2(v1.z, v1.w));
    uint4 r;
    r.x = *(uint32_t*)&h0; r.y = *(uint32_t*)&h1;
    r.z = *(uint32_t*)&h2; r.w = *(uint32_t*)&h3;
    return r;
}

__device__ __forceinline__ void conv16(const float* s, __half* d) {
    float4 v0 = *(const float4*)(s);
    float4 v1 = *(const float4*)(s + 4);
    float4 v2 = *(const float4*)(s + 8);
    float4 v3 = *(const float4*)(s + 12);
    *(uint4*)d       = pack8(v0, v1);
    *(uint4*)(d + 8) = pack8(v2, v3);
}

// Single prep kernel: classify (warp-aggregated) + proj conv + emb-row conv.
__global__ void k_prep(const int* __restrict__ inp,
                       const float* __restrict__ e0, const float* __restrict__ e1,
                       const float* __restrict__ e2, const float* __restrict__ e3,
                       const float* __restrict__ p0, const float* __restrict__ p1,
                       const float* __restrict__ p2, const float* __restrict__ p3)
{
    const int tid = threadIdx.x;
    const int b   = blockIdx.x;

    // ---- classify: blocks 0..63, one atomic per warp per cluster ----
    if (b < NTOK / 256) {
        int t = b * 256 + tid;
        int tok = inp[t];
        int c = (tok >= 200000) ? 3 : (tok >= 40000) ? 2 : (tok >= 20000) ? 1 : 0;
        unsigned m = __match_any_sync(0xffffffffu, c);
        int lane = tid & 31;
        int leader = __ffs(m) - 1;
        int base = 0;
        if (lane == leader) base = atomicAdd(&g_count[c], __popc(m));
        base = __shfl_sync(0xffffffffu, base, leader);
        int rank = __popc(m & ((1u << lane) - 1));
        g_perm[c * NTOK + base + rank] = t;
    }

    // ---- conversion: grid-stride over proj units then emb units ----
    const size_t stride = (size_t)gridDim.x * blockDim.x;
    for (size_t u = (size_t)b * blockDim.x + tid; u < NB16 + NA16; u += stride) {
        if (u < NB16) {
            size_t e = u * 16;
            const float* p; size_t off;
            if (e < B1)      { p = p0; off = e - B0; }
            else if (e < B2) { p = p1; off = e - B1; }
            else if (e < B3) { p = p2; off = e - B2; }
            else             { p = p3; off = e - B3; }
            conv16(p + off, g_bh + e);
        } else {
            size_t w = u - NB16;
            int t    = (int)(w >> 6);
            int koff = (int)(w & 63) << 4;
            int tok  = inp[t];
            const float* src; int D, lo; size_t baseA;
            if      (tok < 20000)  { src = e0; D = 1024; lo = 0;      baseA = A0; }
            else if (tok < 40000)  { src = e1; D = 256;  lo = 20000;  baseA = A1; }
            else if (tok < 200000) { src = e2; D = 64;   lo = 40000;  baseA = A2; }
            else                   { src = e3; D = 16;   lo = 200000; baseA = A3; }
            if (koff < D)
                conv16(src + (size_t)(tok - lo) * D + koff,
                       g_ah + baseA + (size_t)t * D + koff);
        }
    }
}

__device__ __forceinline__ void cp16(uint32_t dst, const void* src, int valid) {
    asm volatile("cp.async.cg.shared.global [%0], [%1], 16, %2;"
                 :: "r"(dst), "l"(src), "r"(valid));
}
__device__ __forceinline__ void ldm4(uint32_t& r0, uint32_t& r1,
                                     uint32_t& r2, uint32_t& r3, uint32_t addr) {
    asm volatile("ldmatrix.sync.aligned.m8n8.x4.shared.b16 {%0,%1,%2,%3}, [%4];"
                 : "=r"(r0), "=r"(r1), "=r"(r2), "=r"(r3) : "r"(addr));
}

// Fused GEMM: C[m,n] = 32 * sum_k A[m,k] * B[n,k]; fp16 smem, ldmatrix frags.
__global__ void __launch_bounds__(256, 2)
k_fused(float* __restrict__ out)
{
    extern __shared__ __half smh[];
    __half* As = smh;                                   // [STAGES][BM][HSTRIDE]
    __half* Bs = smh + STAGES * BM * HSTRIDE;           // [STAGES][BN][HSTRIDE]
    int* s_tok = (int*)(Bs + STAGES * BN * HSTRIDE);    // [BM]

    // ---- map blockIdx.y -> (cluster, mtile) ----
    int y = blockIdx.y;
    int cluster = -1, mtile = 0, acc = 0;
#pragma unroll
    for (int c = 0; c < 4; c++) {
        int tiles = (g_count[c] + BM - 1) >> 7;
        if (cluster < 0 && y < acc + tiles) { cluster = c; mtile = y - acc; }
        acc += tiles;
    }
    if (cluster < 0) return;

    int D; size_t baseA, baseB;
    switch (cluster) {
        case 0:  D = 1024; baseA = A0; baseB = B0; break;
        case 1:  D = 256;  baseA = A1; baseB = B1; break;
        case 2:  D = 64;   baseA = A2; baseB = B2; break;
        default: D = 16;   baseA = A3; baseB = B3; break;
    }

    const int tid = threadIdx.x;
    const int cnt = g_count[cluster];

    if (tid < BM) {
        int m = mtile * BM + tid;
        s_tok[tid] = (m < cnt) ? g_perm[cluster * NTOK + m] : -1;
    }
    __syncthreads();   // s_tok needed by loaders below

    // ---- loader mapping: 2 threads/row, 16 halves each ----
    const int lrow = tid >> 1;
    const int lh   = (tid & 1) * 16;
    const int nb   = blockIdx.x * BN;

    const int atok = s_tok[lrow];
    const int arow_ok = (atok >= 0);
    const __half* asrc = g_ah + baseA + (size_t)(arow_ok ? atok : 0) * D + lh;
    const __half* bsrc = g_bh + baseB + (size_t)(nb + lrow) * D + lh;

    const uint32_t a_smem = (uint32_t)__cvta_generic_to_shared(As) + (lrow * HSTRIDE + lh) * 2;
    const uint32_t b_smem = (uint32_t)__cvta_generic_to_shared(Bs) + (lrow * HSTRIDE + lh) * 2;

    const int nk = (D + BK - 1) / BK;

#define ISSUE(kbi)                                                            \
    do {                                                                      \
        int _buf = (kbi) % STAGES;                                            \
        int _kb  = (kbi) * BK;                                                \
        int _kok = (_kb + lh < D);                                            \
        int _va  = (_kok && arow_ok) ? 16 : 0;                                \
        int _vb  = _kok ? 16 : 0;                                             \
        const __half* _as = _kok ? asrc + _kb : asrc;                         \
        const __half* _bs = _kok ? bsrc + _kb : bsrc;                         \
        uint32_t _ad = a_smem + _buf * (BM * HSTRIDE * 2);                    \
        uint32_t _bd = b_smem + _buf * (BN * HSTRIDE * 2);                    \
        cp16(_ad,      _as,     _va);                                        \
        cp16(_ad + 16, _as + 8, _va);                                        \
        cp16(_bd,      _bs,     _vb);                                        \
        cp16(_bd + 16, _bs + 8, _vb);                                        \
    } while (0)

#pragma unroll
    for (int s = 0; s < STAGES - 1; s++) {
        if (s < nk) ISSUE(s);
        asm volatile("cp.async.commit_group;");
    }

    // ---- warp / fragment mapping: 8 warps = 4m x 2n, warp tile 32x64 ----
    const int wid  = tid >> 5, lane = tid & 31;
    const int gid  = lane >> 2, tg = lane & 3;
    const int wm   = (wid >> 1) * 32;
    const int wn   = (wid & 1) * 64;

    // ldmatrix address offsets (bytes) within a stage
    const int l8   = lane & 7;
    const int lb8  = (lane >> 3) & 1;
    const int lb16 = (lane >> 4) & 1;
    uint32_t a_off[2], b_off[4];
#pragma unroll
    for (int mi = 0; mi < 2; mi++)
        a_off[mi] = ((wm + mi * 16 + lb8 * 8 + l8) * HSTRIDE + lb16 * 8) * 2;
#pragma unroll
    for (int j = 0; j < 4; j++)
        b_off[j] = ((wn + j * 16 + lb16 * 8 + l8) * HSTRIDE + lb8 * 8) * 2;

    const uint32_t As_u = (uint32_t)__cvta_generic_to_shared(As);
    const uint32_t Bs_u = (uint32_t)__cvta_generic_to_shared(Bs);

    float accum[2][8][4];
#pragma unroll
    for (int i = 0; i < 2; i++)
#pragma unroll
        for (int j = 0; j < 8; j++)
#pragma unroll
            for (int k = 0; k < 4; k++) accum[i][j][k] = 0.f;

    for (int kbi = 0; kbi < nk; kbi++) {
        asm volatile("cp.async.wait_group 1;");
        __syncthreads();

        const uint32_t Abu = As_u + (kbi % STAGES) * (BM * HSTRIDE * 2);
        const uint32_t Bbu = Bs_u + (kbi % STAGES) * (BN * HSTRIDE * 2);

#pragma unroll
        for (int ks = 0; ks < 2; ks++) {
            const int kkb = ks * 32;   // byte offset of k sub-block
            uint32_t a[2][4], b[8][2];
#pragma unroll
            for (int mi = 0; mi < 2; mi++)
                ldm4(a[mi][0], a[mi][1], a[mi][2], a[mi][3], Abu + a_off[mi] + kkb);
#pragma unroll
            for (int j = 0; j < 4; j++)
                ldm4(b[2*j][0], b[2*j][1], b[2*j+1][0], b[2*j+1][1],
                     Bbu + b_off[j] + kkb);
#pragma unroll
            for (int mi = 0; mi < 2; mi++)
#pragma unroll
                for (int ni = 0; ni < 8; ni++) {
                    asm volatile(
                        "mma.sync.aligned.m16n8k16.row.col.f32.f16.f16.f32 "
                        "{%0,%1,%2,%3}, {%4,%5,%6,%7}, {%8,%9}, {%0,%1,%2,%3};"
                        : "+f"(accum[mi][ni][0]), "+f"(accum[mi][ni][1]),
                          "+f"(accum[mi][ni][2]), "+f"(accum[mi][ni][3])
                        : "r"(a[mi][0]), "r"(a[mi][1]), "r"(a[mi][2]), "r"(a[mi][3]),
                          "r"(b[ni][0]), "r"(b[ni][1]));
                }
        }

        int pf = kbi + STAGES - 1;
        if (pf < nk) ISSUE(pf);
        asm volatile("cp.async.commit_group;");
    }
#undef ISSUE

    // ---- epilogue: scale by 32, scatter to out[token, :] ----
#pragma unroll
    for (int mi = 0; mi < 2; mi++) {
#pragma unroll
        for (int half = 0; half < 2; half++) {
            int rl = wm + mi * 16 + gid + half * 8;
            int t  = s_tok[rl];
            if (t >= 0) {
                float* op = out + (size_t)t * DPROJ + nb + wn;
#pragma unroll
                for (int ni = 0; ni < 8; ni++) {
                    float2 v;
                    v.x = accum[mi][ni][half * 2 + 0] * 32.f;
                    v.y = accum[mi][ni][half * 2 + 1] * 32.f;
                    *(float2*)(op + ni * 8 + tg * 2) = v;
                }
            }
        }
    }
}

extern "C" void kernel_launch(void* const* d_in, const int* in_sizes, int n_in,
                              void* d_out, int out_size) {
    const int*   inp   = (const int*)d_in[0];
    const float* emb0  = (const float*)d_in[1];
    const float* proj0 = (const float*)d_in[2];
    const float* emb1  = (const float*)d_in[3];
    const float* proj1 = (const float*)d_in[4];
    const float* emb2  = (const float*)d_in[5];
    const float* proj2 = (const float*)d_in[6];
    const float* emb3  = (const float*)d_in[7];
    const float* proj3 = (const float*)d_in[8];
    float* out = (float*)d_out;

    const int smem_bytes = STAGES * (BM + BN) * HSTRIDE * 2 + BM * 4;
    cudaFuncSetAttribute(k_fused, cudaFuncAttributeMaxDynamicSharedMemorySize,
                         smem_bytes);

    void* gcnt = nullptr;
    cudaGetSymbolAddress(&gcnt, g_count);
    cudaMemsetAsync(gcnt, 0, 4 * sizeof(int));

    k_prep<<<1024, 256>>>(inp, emb0, emb1, emb2, emb3,
                          proj0, proj1, proj2, proj3);

    dim3 grid(DPROJ / BN, MAX_MTILES);   // (8, 132)
    k_fused<<<grid, 256, smem_bytes>>>(out);
}